// round 6
// baseline (speedup 1.0000x reference)
#include <cuda_runtime.h>
#include <math.h>

// Problem constants
#define NB   2
#define NS   2048
#define ND   2048
#define NH   16
#define NDH  128
#define MROWS (NB*NS)        // 4096 flattened (b,s) rows
#define FEAT  (NH*NDH)       // 2048 flattened (h,e) features

// Scratch buffers (allocation-free rule: __device__ globals)
#define QKV_ELEMS 8388608ull  // 4096 * 2048
__device__ float g_q[QKV_ELEMS];
__device__ float g_k[QKV_ELEMS];
__device__ float g_v[QKV_ELEMS];
__device__ float g_z[QKV_ELEMS];

// ---------------------------------------------------------------------------
// SGEMM: C[4096 x 128-per-ntile] = A[4096 x K] * B + bias
// Block tile 128x128, BK=8, 256 threads, 8x8 microtile, DOUBLE-BUFFERED smem
// (gmem prefetch into regs overlapped with compute; one barrier per K-slice).
// B tile base = B + ntile*btileStride, element [k][j] = base[k*ldb + j].
//   projections: btileStride = D*128 (per-head weight slab), ldb = 128
//   out-proj   : btileStride = 128  (column offset),          ldb = 2048
// ---------------------------------------------------------------------------
__global__ __launch_bounds__(256) void sgemm128(
    const float* __restrict__ A, const float* __restrict__ B,
    const float* __restrict__ bias, float* __restrict__ C,
    int K, int lda, int ldb, long long btileStride, int ldc)
{
    __shared__ float As[2][8][132];   // transposed: As[buf][k][m]
    __shared__ float Bs[2][8][132];   // Bs[buf][k][n]

    const int tid = threadIdx.x;
    const int mtile = blockIdx.x, ntile = blockIdx.y;

    const int arow = tid >> 1, acol = (tid & 1) * 4;
    const int brow = tid >> 5, bcol = (tid & 31) * 4;

    const float* Ap = A + (size_t)(mtile * 128 + arow) * lda + acol;
    const float* Bp = B + (size_t)ntile * btileStride + (size_t)brow * ldb + bcol;

    const int tx = tid & 15, ty = tid >> 4;

    float acc[8][8];
#pragma unroll
    for (int i = 0; i < 8; i++)
#pragma unroll
        for (int j = 0; j < 8; j++) acc[i][j] = 0.0f;

    // Preload slice 0 into buffer 0
    {
        float4 a = *(const float4*)Ap;
        float4 b = *(const float4*)Bp;
        As[0][acol + 0][arow] = a.x;
        As[0][acol + 1][arow] = a.y;
        As[0][acol + 2][arow] = a.z;
        As[0][acol + 3][arow] = a.w;
        *(float4*)&Bs[0][brow][bcol] = b;
    }
    __syncthreads();

    const int nt = K >> 3;
    int buf = 0;
    for (int kt = 0; kt < nt; kt++) {
        float4 an, bn;
        const bool more = (kt + 1 < nt);
        if (more) {
            Ap += 8;
            Bp += (size_t)8 * ldb;
            an = *(const float4*)Ap;     // prefetch next slice (regs)
            bn = *(const float4*)Bp;
        }

#pragma unroll
        for (int k = 0; k < 8; k++) {
            float ar[8], br[8];
            *(float4*)(ar)     = *(float4*)&As[buf][k][ty * 8];
            *(float4*)(ar + 4) = *(float4*)&As[buf][k][ty * 8 + 4];
            *(float4*)(br)     = *(float4*)&Bs[buf][k][tx * 8];
            *(float4*)(br + 4) = *(float4*)&Bs[buf][k][tx * 8 + 4];
#pragma unroll
            for (int i = 0; i < 8; i++)
#pragma unroll
                for (int j = 0; j < 8; j++)
                    acc[i][j] += ar[i] * br[j];
        }

        if (more) {
            int nb = buf ^ 1;
            As[nb][acol + 0][arow] = an.x;
            As[nb][acol + 1][arow] = an.y;
            As[nb][acol + 2][arow] = an.z;
            As[nb][acol + 3][arow] = an.w;
            *(float4*)&Bs[nb][brow][bcol] = bn;
            __syncthreads();
            buf = nb;
        }
    }

    // Epilogue: bias add + store
#pragma unroll
    for (int i = 0; i < 8; i++) {
        size_t row = (size_t)(mtile * 128 + ty * 8 + i);
        float* cp = C + row * ldc + ntile * 128 + tx * 8;
        const float* bp = bias + ntile * 128 + tx * 8;
        float4 o0, o1;
        o0.x = acc[i][0] + bp[0]; o0.y = acc[i][1] + bp[1];
        o0.z = acc[i][2] + bp[2]; o0.w = acc[i][3] + bp[3];
        o1.x = acc[i][4] + bp[4]; o1.y = acc[i][5] + bp[5];
        o1.z = acc[i][6] + bp[6]; o1.w = acc[i][7] + bp[7];
        *(float4*)(cp)     = o0;
        *(float4*)(cp + 4) = o1;
    }
}

// ---------------------------------------------------------------------------
// Rotary (in-place on q and k). One thread per (b,s,h,pair) with pair (e,e+64).
// rotated[e]    = x[e]*cos(a_e)    - x[e+64]*sin(a_e)
// rotated[e+64] = x[e+64]*cos(a_e) + x[e]*sin(a_e)     (same angle, freq[e+64]=freq[e])
// ---------------------------------------------------------------------------
__global__ void rotary_kernel(float* __restrict__ q, float* __restrict__ k)
{
    int p = blockIdx.x * blockDim.x + threadIdx.x;   // 0 .. 2^22-1
    int e = p & 63;
    int h = (p >> 6) & 15;
    int s = (p >> 10) & 2047;
    int b = p >> 21;

    float freq = powf(10000.0f, (float)e * (1.0f / 64.0f));
    float ang  = (float)s / freq;
    float sn, cs;
    sincosf(ang, &sn, &cs);

    size_t base = ((size_t)(b * NS + s) * NH + h) * NDH + e;

    float x0 = q[base], x1 = q[base + 64];
    q[base]      = x0 * cs - x1 * sn;
    q[base + 64] = x1 * cs + x0 * sn;

    x0 = k[base]; x1 = k[base + 64];
    k[base]      = x0 * cs - x1 * sn;
    k[base + 64] = x1 * cs + x0 * sn;
}

// ---------------------------------------------------------------------------
// Flash attention (causal, fp32). Br=Bc=64, 256 threads (8 warps x 8 rows).
// smem: Qs/Ks/Vs [64][132] (pitch 132 floats -> float4 conflict-free), Ps[64][68].
// Per lane: 2 keys in QK (lane, lane+32), 4 contiguous output cols in PV.
// ---------------------------------------------------------------------------
#define FLASH_SMEM ((3 * 64 * 132 + 64 * 68) * 4)   // 118784 bytes

__global__ __launch_bounds__(256, 1) void flash_kernel(
    const float* __restrict__ gq, const float* __restrict__ gk,
    const float* __restrict__ gv, float* __restrict__ gz)
{
    extern __shared__ float sm[];
    float* Qs = sm;                 // [64][132]
    float* Ks = sm + 64 * 132;      // [64][132]
    float* Vs = sm + 2 * 64 * 132;  // [64][132]
    float* Ps = sm + 3 * 64 * 132;  // [64][68]

    const int tid = threadIdx.x;
    const int lane = tid & 31;
    const int w = tid >> 5;                 // warp id: owns rows w*8 .. w*8+7
    const int qt = blockIdx.x;              // query tile
    const int h = blockIdx.y;
    const int b = blockIdx.z;

    const size_t hb = (size_t)b * ((size_t)NS * NH * NDH) + (size_t)h * NDH;
    const float* qb = gq + hb;
    const float* kb = gk + hb;
    const float* vb = gv + hb;
    float* zb = gz + hb;

    const float scale = 0.08838834764831845f;   // 1/sqrt(128)
    const int ldrow = NH * NDH;                 // 2048

    // Load + pre-scale Q tile
    {
        const int r0 = tid >> 5, c = (tid & 31) * 4;
#pragma unroll
        for (int i = 0; i < 8; i++) {
            int r = r0 + i * 8;
            float4 qv = *(const float4*)(qb + (size_t)(qt * 64 + r) * ldrow + c);
            qv.x *= scale; qv.y *= scale; qv.z *= scale; qv.w *= scale;
            *(float4*)&Qs[r * 132 + c] = qv;
        }
    }

    float m_i[8], l_i[8], O[8][4];
#pragma unroll
    for (int i = 0; i < 8; i++) {
        m_i[i] = -INFINITY; l_i[i] = 0.0f;
        O[i][0] = O[i][1] = O[i][2] = O[i][3] = 0.0f;
    }

    const int c0 = lane * 4;

    for (int j = 0; j <= qt; j++) {
        __syncthreads();   // previous tile fully consumed; Q visible on j=0
        {
            const int r0 = tid >> 5, c = (tid & 31) * 4;
#pragma unroll
            for (int i = 0; i < 8; i++) {
                int r = r0 + i * 8;
                size_t gofs = (size_t)(j * 64 + r) * ldrow + c;
                *(float4*)&Ks[r * 132 + c] = *(const float4*)(kb + gofs);
                *(float4*)&Vs[r * 132 + c] = *(const float4*)(vb + gofs);
            }
        }
        __syncthreads();

        // --- S = Q K^T (this lane: keys `lane` and `lane+32`) ---
        float sA[8], sB[8];
#pragma unroll
        for (int i = 0; i < 8; i++) { sA[i] = 0.0f; sB[i] = 0.0f; }

#pragma unroll 2
        for (int e = 0; e < 128; e += 4) {
            float4 k0 = *(float4*)&Ks[lane * 132 + e];
            float4 k1 = *(float4*)&Ks[(lane + 32) * 132 + e];
#pragma unroll
            for (int i = 0; i < 8; i++) {
                float4 qv = *(float4*)&Qs[(w * 8 + i) * 132 + e];
                sA[i] += qv.x * k0.x + qv.y * k0.y + qv.z * k0.z + qv.w * k0.w;
                sB[i] += qv.x * k1.x + qv.y * k1.y + qv.z * k1.z + qv.w * k1.w;
            }
        }

        // Causal mask on the diagonal tile
        if (j == qt) {
#pragma unroll
            for (int i = 0; i < 8; i++) {
                int ql = w * 8 + i;
                if (lane > ql)      sA[i] = -INFINITY;
                if (lane + 32 > ql) sB[i] = -INFINITY;
            }
        }

        // --- online softmax update per row ---
#pragma unroll
        for (int i = 0; i < 8; i++) {
            float rmax = fmaxf(sA[i], sB[i]);
#pragma unroll
            for (int off = 16; off > 0; off >>= 1)
                rmax = fmaxf(rmax, __shfl_xor_sync(0xffffffffu, rmax, off));
            float mn = fmaxf(m_i[i], rmax);
            float alpha = __expf(m_i[i] - mn);
            float p0 = __expf(sA[i] - mn);
            float p1 = __expf(sB[i] - mn);
            float ps = p0 + p1;
#pragma unroll
            for (int off = 16; off > 0; off >>= 1)
                ps += __shfl_xor_sync(0xffffffffu, ps, off);
            l_i[i] = l_i[i] * alpha + ps;
            m_i[i] = mn;
            O[i][0] *= alpha; O[i][1] *= alpha; O[i][2] *= alpha; O[i][3] *= alpha;
            Ps[(w * 8 + i) * 68 + lane]      = p0;
            Ps[(w * 8 + i) * 68 + lane + 32] = p1;
        }
        __syncwarp();

        // --- O += P V (this lane: cols c0..c0+3) ---
#pragma unroll 2
        for (int k = 0; k < 64; k += 4) {
            float4 v0 = *(float4*)&Vs[(k + 0) * 132 + c0];
            float4 v1 = *(float4*)&Vs[(k + 1) * 132 + c0];
            float4 v2 = *(float4*)&Vs[(k + 2) * 132 + c0];
            float4 v3 = *(float4*)&Vs[(k + 3) * 132 + c0];
#pragma unroll
            for (int i = 0; i < 8; i++) {
                float4 p4 = *(float4*)&Ps[(w * 8 + i) * 68 + k];
                O[i][0] += p4.x * v0.x + p4.y * v1.x + p4.z * v2.x + p4.w * v3.x;
                O[i][1] += p4.x * v0.y + p4.y * v1.y + p4.z * v2.y + p4.w * v3.y;
                O[i][2] += p4.x * v0.z + p4.y * v1.z + p4.z * v2.z + p4.w * v3.z;
                O[i][3] += p4.x * v0.w + p4.y * v1.w + p4.z * v2.w + p4.w * v3.w;
            }
        }
        __syncwarp();
    }

    // Epilogue: normalize and store
#pragma unroll
    for (int i = 0; i < 8; i++) {
        float inv = 1.0f / l_i[i];
        int rg = qt * 64 + w * 8 + i;
        float4 o;
        o.x = O[i][0] * inv; o.y = O[i][1] * inv;
        o.z = O[i][2] * inv; o.w = O[i][3] * inv;
        *(float4*)(zb + (size_t)rg * ldrow + c0) = o;
    }
}

// ---------------------------------------------------------------------------
// Launcher
// Inputs: 0 query, 1 key, 2 value, 3 W_Q, 4 W_K, 5 W_V, 6 W_O,
//         7 b_Q, 8 b_K, 9 b_V, 10 b_O.  Output: [B,S,D] fp32.
// ---------------------------------------------------------------------------
extern "C" void kernel_launch(void* const* d_in, const int* in_sizes, int n_in,
                              void* d_out, int out_size)
{
    const float* xq = (const float*)d_in[0];
    const float* xk = (const float*)d_in[1];
    const float* xv = (const float*)d_in[2];
    const float* WQ = (const float*)d_in[3];
    const float* WK = (const float*)d_in[4];
    const float* WV = (const float*)d_in[5];
    const float* WO = (const float*)d_in[6];
    const float* bQ = (const float*)d_in[7];
    const float* bK = (const float*)d_in[8];
    const float* bV = (const float*)d_in[9];
    const float* bO = (const float*)d_in[10];
    float* out = (float*)d_out;

    float *qp, *kp, *vp, *zp;
    cudaGetSymbolAddress((void**)&qp, g_q);
    cudaGetSymbolAddress((void**)&kp, g_k);
    cudaGetSymbolAddress((void**)&vp, g_v);
    cudaGetSymbolAddress((void**)&zp, g_z);

    dim3 gg(MROWS / 128, FEAT / 128);   // (32, 16)

    // QKV projections (per-head weight slabs: stride D*128, ldb=128)
    const long long projStride = (long long)ND * NDH;  // 262144
    sgemm128<<<gg, 256>>>(xq, WQ, bQ, qp, ND, ND, NDH, projStride, FEAT);
    sgemm128<<<gg, 256>>>(xk, WK, bK, kp, ND, ND, NDH, projStride, FEAT);
    sgemm128<<<gg, 256>>>(xv, WV, bV, vp, ND, ND, NDH, projStride, FEAT);

    // Rotary on q and k (4,194,304 pairs)
    rotary_kernel<<<16384, 256>>>(qp, kp);

    // Flash attention
    cudaFuncSetAttribute(flash_kernel,
                         cudaFuncAttributeMaxDynamicSharedMemorySize, FLASH_SMEM);
    flash_kernel<<<dim3(NS / 64, NH, NB), 256, FLASH_SMEM>>>(qp, kp, vp, zp);

    // Output projection: z[4096,2048] @ W_O[2048,2048] + b_O
    sgemm128<<<gg, 256>>>(zp, WO, bO, out, FEAT, FEAT, ND, 128LL, ND);
}

// round 7
// speedup vs baseline: 1.2509x; 1.2509x over previous
#include <cuda_runtime.h>
#include <math.h>
#include <stdint.h>

// Problem constants
#define NB   2
#define NS   2048
#define ND   2048
#define NH   16
#define NDH  128
#define MROWS (NB*NS)        // 4096 flattened (b,s) rows
#define FEAT  (NH*NDH)       // 2048 flattened (h,e) features

// Scratch buffers (allocation-free rule: __device__ globals)
#define QKV_ELEMS 8388608ull  // 4096 * 2048
__device__ float g_q[QKV_ELEMS];
__device__ float g_k[QKV_ELEMS];
__device__ float g_v[QKV_ELEMS];
__device__ float g_z[QKV_ELEMS];

// ---------------------------------------------------------------------------
// 3xTF32 tensor-core GEMM: C[4096 x 128-per-ntile] = A[4096 x K] * B + bias
// Block tile 128x128, BK=32, 256 threads = 8 warps in 2(m) x 4(n) grid,
// warp tile 64x32 = 4x4 m16n8k8 mma tiles. cp.async double-buffered smem.
// Split trick: A=Ahi+Alo, B=Bhi+Blo (tf32 rounding), D += Ahi*Bhi+Ahi*Blo+Alo*Bhi
// -> ~2^-22 relative error (near-fp32) at tensor-core speed.
// B tile base = B + ntile*btileStride, element [k][j] = base[k*ldb + j].
//   projections: btileStride = D*128 (per-head weight slab), ldb = 128
//   out-proj   : btileStride = 128  (column offset),          ldb = 2048
// ---------------------------------------------------------------------------
#define BK      32
#define APITCH  36                    // A smem pitch (floats): bank 4m+k, conflict-free
#define BPITCH  136                   // B smem pitch (floats): bank 8k+n, conflict-free
#define A_SM    (128 * APITCH)        // 4608 floats
#define B_SM    (BK * BPITCH)         // 4352 floats
#define BUF_SM  (A_SM + B_SM)         // 8960 floats per buffer
#define GEMM_SMEM (2 * BUF_SM * 4)    // 71680 bytes

__device__ __forceinline__ void split_tf32(float x, uint32_t& hi, uint32_t& lo)
{
    uint32_t h;
    asm("cvt.rna.tf32.f32 %0, %1;" : "=r"(h) : "f"(x));
    float r = x - __uint_as_float(h);
    asm("cvt.rna.tf32.f32 %0, %1;" : "=r"(lo) : "f"(r));
    hi = h;
}

__device__ __forceinline__ void mma_tf32(float* d, const uint32_t* a, const uint32_t* b)
{
    asm volatile(
        "mma.sync.aligned.m16n8k8.row.col.f32.tf32.tf32.f32 "
        "{%0,%1,%2,%3}, {%4,%5,%6,%7}, {%8,%9}, {%0,%1,%2,%3};\n"
        : "+f"(d[0]), "+f"(d[1]), "+f"(d[2]), "+f"(d[3])
        : "r"(a[0]), "r"(a[1]), "r"(a[2]), "r"(a[3]), "r"(b[0]), "r"(b[1]));
}

__device__ __forceinline__ void cp16(uint32_t smem_addr, const void* gptr)
{
    asm volatile("cp.async.cg.shared.global [%0], [%1], 16;\n"
                 :: "r"(smem_addr), "l"(gptr));
}

__global__ __launch_bounds__(256) void tf32gemm128(
    const float* __restrict__ A, const float* __restrict__ B,
    const float* __restrict__ bias, float* __restrict__ C,
    int K, int lda, int ldb, long long btileStride, int ldc)
{
    extern __shared__ float sm[];
    const uint32_t sm_u = (uint32_t)__cvta_generic_to_shared(sm);

    const int tid  = threadIdx.x;
    const int lane = tid & 31;
    const int w    = tid >> 5;
    const int warpM = w >> 2;          // 0..1
    const int warpN = w & 3;           // 0..3
    const int g  = lane >> 2;          // mma groupID (0..7)
    const int tg = lane & 3;           // mma thread-in-group (0..3)

    const int mtile = blockIdx.x, ntile = blockIdx.y;

    const float* Abase = A + (size_t)(mtile * 128) * lda;
    const float* Bbase = B + (size_t)ntile * btileStride;

    // gmem->smem mapping (per thread, 4 x 16B each for A and B)
    const int a_kq = tid & 7;          // float4 index along k (0..7)
    const int a_m0 = tid >> 3;         // row base (0..31), +32*i
    const int b_n4 = tid & 31;         // float4 index along n (0..31)
    const int b_k0 = tid >> 5;         // k base (0..7), +8*i

    float acc[16][4];                  // [mt*4+nt][frag]
#pragma unroll
    for (int i = 0; i < 16; i++)
#pragma unroll
        for (int j = 0; j < 4; j++) acc[i][j] = 0.0f;

    const int nt_iters = K >> 5;       // 64

    // ---- issue loads for k-tile `kt` into buffer `bf` ----
#define ISSUE_TILE(kt, bf)                                                        \
    {                                                                             \
        uint32_t abuf = sm_u + (uint32_t)((bf) * BUF_SM) * 4u;                    \
        uint32_t bbuf = abuf + (uint32_t)A_SM * 4u;                               \
        _Pragma("unroll")                                                         \
        for (int i = 0; i < 4; i++) {                                             \
            int m = a_m0 + 32 * i;                                                \
            cp16(abuf + (uint32_t)(m * APITCH + a_kq * 4) * 4u,                   \
                 Abase + (size_t)m * lda + (kt) * BK + a_kq * 4);                 \
        }                                                                         \
        _Pragma("unroll")                                                         \
        for (int i = 0; i < 4; i++) {                                             \
            int k = b_k0 + 8 * i;                                                 \
            cp16(bbuf + (uint32_t)(k * BPITCH + b_n4 * 4) * 4u,                   \
                 Bbase + (size_t)((kt) * BK + k) * ldb + b_n4 * 4);               \
        }                                                                         \
        asm volatile("cp.async.commit_group;\n" ::);                              \
    }

    ISSUE_TILE(0, 0);

    int buf = 0;
    for (int kt = 0; kt < nt_iters; kt++) {
        if (kt + 1 < nt_iters) {
            ISSUE_TILE(kt + 1, buf ^ 1);
            asm volatile("cp.async.wait_group 1;\n" ::);
        } else {
            asm volatile("cp.async.wait_group 0;\n" ::);
        }
        __syncthreads();

        const float* Asb = sm + buf * BUF_SM;
        const float* Bsb = Asb + A_SM;

#pragma unroll
        for (int ks = 0; ks < 4; ks++) {
            const int k0 = ks * 8;

            // B fragments for the warp's 4 n-tiles
            uint32_t bhi[4][2], blo[4][2];
#pragma unroll
            for (int nt = 0; nt < 4; nt++) {
                int n = warpN * 32 + nt * 8 + g;
                float b0 = Bsb[(k0 + tg) * BPITCH + n];
                float b1 = Bsb[(k0 + tg + 4) * BPITCH + n];
                split_tf32(b0, bhi[nt][0], blo[nt][0]);
                split_tf32(b1, bhi[nt][1], blo[nt][1]);
            }

#pragma unroll
            for (int mt = 0; mt < 4; mt++) {
                int m = warpM * 64 + mt * 16 + g;
                float a0 = Asb[m * APITCH + k0 + tg];
                float a1 = Asb[(m + 8) * APITCH + k0 + tg];
                float a2 = Asb[m * APITCH + k0 + tg + 4];
                float a3 = Asb[(m + 8) * APITCH + k0 + tg + 4];
                uint32_t ahi[4], alo[4];
                split_tf32(a0, ahi[0], alo[0]);
                split_tf32(a1, ahi[1], alo[1]);
                split_tf32(a2, ahi[2], alo[2]);
                split_tf32(a3, ahi[3], alo[3]);
#pragma unroll
                for (int nt = 0; nt < 4; nt++) {
                    float* d = acc[mt * 4 + nt];
                    mma_tf32(d, ahi, bhi[nt]);
                    mma_tf32(d, ahi, blo[nt]);
                    mma_tf32(d, alo, bhi[nt]);
                }
            }
        }

        __syncthreads();   // all warps done with `buf` before it is refilled
        buf ^= 1;
    }

    // Epilogue: bias add + store (c0/c1 adjacent cols -> float2)
#pragma unroll
    for (int mt = 0; mt < 4; mt++) {
#pragma unroll
        for (int nt = 0; nt < 4; nt++) {
            const float* d = acc[mt * 4 + nt];
            int r0 = mtile * 128 + warpM * 64 + mt * 16 + g;
            int c  = ntile * 128 + warpN * 32 + nt * 8 + 2 * tg;
            float bx = bias[c], by = bias[c + 1];
            float2 lo = make_float2(d[0] + bx, d[1] + by);
            float2 hi = make_float2(d[2] + bx, d[3] + by);
            *(float2*)&C[(size_t)r0 * ldc + c]       = lo;
            *(float2*)&C[(size_t)(r0 + 8) * ldc + c] = hi;
        }
    }
}

// ---------------------------------------------------------------------------
// Rotary (in-place on q and k). One thread per (b,s,h,pair) with pair (e,e+64).
// ---------------------------------------------------------------------------
__global__ void rotary_kernel(float* __restrict__ q, float* __restrict__ k)
{
    int p = blockIdx.x * blockDim.x + threadIdx.x;   // 0 .. 2^22-1
    int e = p & 63;
    int h = (p >> 6) & 15;
    int s = (p >> 10) & 2047;
    int b = p >> 21;

    float freq = powf(10000.0f, (float)e * (1.0f / 64.0f));
    float ang  = (float)s / freq;
    float sn, cs;
    sincosf(ang, &sn, &cs);

    size_t base = ((size_t)(b * NS + s) * NH + h) * NDH + e;

    float x0 = q[base], x1 = q[base + 64];
    q[base]      = x0 * cs - x1 * sn;
    q[base + 64] = x1 * cs + x0 * sn;

    x0 = k[base]; x1 = k[base + 64];
    k[base]      = x0 * cs - x1 * sn;
    k[base + 64] = x1 * cs + x0 * sn;
}

// ---------------------------------------------------------------------------
// Flash attention (causal, fp32). Br=Bc=64, 256 threads (8 warps x 8 rows).
// (unchanged from the passing R5 kernel; tf32 conversion is the next lever)
// ---------------------------------------------------------------------------
#define FLASH_SMEM ((3 * 64 * 132 + 64 * 68) * 4)   // 118784 bytes

__global__ __launch_bounds__(256, 1) void flash_kernel(
    const float* __restrict__ gq, const float* __restrict__ gk,
    const float* __restrict__ gv, float* __restrict__ gz)
{
    extern __shared__ float sm[];
    float* Qs = sm;                 // [64][132]
    float* Ks = sm + 64 * 132;      // [64][132]
    float* Vs = sm + 2 * 64 * 132;  // [64][132]
    float* Ps = sm + 3 * 64 * 132;  // [64][68]

    const int tid = threadIdx.x;
    const int lane = tid & 31;
    const int w = tid >> 5;                 // warp id: owns rows w*8 .. w*8+7
    const int qt = blockIdx.x;              // query tile
    const int h = blockIdx.y;
    const int b = blockIdx.z;

    const size_t hb = (size_t)b * ((size_t)NS * NH * NDH) + (size_t)h * NDH;
    const float* qb = gq + hb;
    const float* kb = gk + hb;
    const float* vb = gv + hb;
    float* zb = gz + hb;

    const float scale = 0.08838834764831845f;   // 1/sqrt(128)
    const int ldrow = NH * NDH;                 // 2048

    // Load + pre-scale Q tile
    {
        const int r0 = tid >> 5, c = (tid & 31) * 4;
#pragma unroll
        for (int i = 0; i < 8; i++) {
            int r = r0 + i * 8;
            float4 qv = *(const float4*)(qb + (size_t)(qt * 64 + r) * ldrow + c);
            qv.x *= scale; qv.y *= scale; qv.z *= scale; qv.w *= scale;
            *(float4*)&Qs[r * 132 + c] = qv;
        }
    }

    float m_i[8], l_i[8], O[8][4];
#pragma unroll
    for (int i = 0; i < 8; i++) {
        m_i[i] = -INFINITY; l_i[i] = 0.0f;
        O[i][0] = O[i][1] = O[i][2] = O[i][3] = 0.0f;
    }

    const int c0 = lane * 4;

    for (int j = 0; j <= qt; j++) {
        __syncthreads();   // previous tile fully consumed; Q visible on j=0
        {
            const int r0 = tid >> 5, c = (tid & 31) * 4;
#pragma unroll
            for (int i = 0; i < 8; i++) {
                int r = r0 + i * 8;
                size_t gofs = (size_t)(j * 64 + r) * ldrow + c;
                *(float4*)&Ks[r * 132 + c] = *(const float4*)(kb + gofs);
                *(float4*)&Vs[r * 132 + c] = *(const float4*)(vb + gofs);
            }
        }
        __syncthreads();

        // --- S = Q K^T (this lane: keys `lane` and `lane+32`) ---
        float sA[8], sB[8];
#pragma unroll
        for (int i = 0; i < 8; i++) { sA[i] = 0.0f; sB[i] = 0.0f; }

#pragma unroll 2
        for (int e = 0; e < 128; e += 4) {
            float4 k0 = *(float4*)&Ks[lane * 132 + e];
            float4 k1 = *(float4*)&Ks[(lane + 32) * 132 + e];
#pragma unroll
            for (int i = 0; i < 8; i++) {
                float4 qv = *(float4*)&Qs[(w * 8 + i) * 132 + e];
                sA[i] += qv.x * k0.x + qv.y * k0.y + qv.z * k0.z + qv.w * k0.w;
                sB[i] += qv.x * k1.x + qv.y * k1.y + qv.z * k1.z + qv.w * k1.w;
            }
        }

        // Causal mask on the diagonal tile
        if (j == qt) {
#pragma unroll
            for (int i = 0; i < 8; i++) {
                int ql = w * 8 + i;
                if (lane > ql)      sA[i] = -INFINITY;
                if (lane + 32 > ql) sB[i] = -INFINITY;
            }
        }

        // --- online softmax update per row ---
#pragma unroll
        for (int i = 0; i < 8; i++) {
            float rmax = fmaxf(sA[i], sB[i]);
#pragma unroll
            for (int off = 16; off > 0; off >>= 1)
                rmax = fmaxf(rmax, __shfl_xor_sync(0xffffffffu, rmax, off));
            float mn = fmaxf(m_i[i], rmax);
            float alpha = __expf(m_i[i] - mn);
            float p0 = __expf(sA[i] - mn);
            float p1 = __expf(sB[i] - mn);
            float ps = p0 + p1;
#pragma unroll
            for (int off = 16; off > 0; off >>= 1)
                ps += __shfl_xor_sync(0xffffffffu, ps, off);
            l_i[i] = l_i[i] * alpha + ps;
            m_i[i] = mn;
            O[i][0] *= alpha; O[i][1] *= alpha; O[i][2] *= alpha; O[i][3] *= alpha;
            Ps[(w * 8 + i) * 68 + lane]      = p0;
            Ps[(w * 8 + i) * 68 + lane + 32] = p1;
        }
        __syncwarp();

        // --- O += P V (this lane: cols c0..c0+3) ---
#pragma unroll 2
        for (int k = 0; k < 64; k += 4) {
            float4 v0 = *(float4*)&Vs[(k + 0) * 132 + c0];
            float4 v1 = *(float4*)&Vs[(k + 1) * 132 + c0];
            float4 v2 = *(float4*)&Vs[(k + 2) * 132 + c0];
            float4 v3 = *(float4*)&Vs[(k + 3) * 132 + c0];
#pragma unroll
            for (int i = 0; i < 8; i++) {
                float4 p4 = *(float4*)&Ps[(w * 8 + i) * 68 + k];
                O[i][0] += p4.x * v0.x + p4.y * v1.x + p4.z * v2.x + p4.w * v3.x;
                O[i][1] += p4.x * v0.y + p4.y * v1.y + p4.z * v2.y + p4.w * v3.y;
                O[i][2] += p4.x * v0.z + p4.y * v1.z + p4.z * v2.z + p4.w * v3.z;
                O[i][3] += p4.x * v0.w + p4.y * v1.w + p4.z * v2.w + p4.w * v3.w;
            }
        }
        __syncwarp();
    }

    // Epilogue: normalize and store
#pragma unroll
    for (int i = 0; i < 8; i++) {
        float inv = 1.0f / l_i[i];
        int rg = qt * 64 + w * 8 + i;
        float4 o;
        o.x = O[i][0] * inv; o.y = O[i][1] * inv;
        o.z = O[i][2] * inv; o.w = O[i][3] * inv;
        *(float4*)(zb + (size_t)rg * ldrow + c0) = o;
    }
}

// ---------------------------------------------------------------------------
// Launcher
// Inputs: 0 query, 1 key, 2 value, 3 W_Q, 4 W_K, 5 W_V, 6 W_O,
//         7 b_Q, 8 b_K, 9 b_V, 10 b_O.  Output: [B,S,D] fp32.
// ---------------------------------------------------------------------------
extern "C" void kernel_launch(void* const* d_in, const int* in_sizes, int n_in,
                              void* d_out, int out_size)
{
    const float* xq = (const float*)d_in[0];
    const float* xk = (const float*)d_in[1];
    const float* xv = (const float*)d_in[2];
    const float* WQ = (const float*)d_in[3];
    const float* WK = (const float*)d_in[4];
    const float* WV = (const float*)d_in[5];
    const float* WO = (const float*)d_in[6];
    const float* bQ = (const float*)d_in[7];
    const float* bK = (const float*)d_in[8];
    const float* bV = (const float*)d_in[9];
    const float* bO = (const float*)d_in[10];
    float* out = (float*)d_out;

    float *qp, *kp, *vp, *zp;
    cudaGetSymbolAddress((void**)&qp, g_q);
    cudaGetSymbolAddress((void**)&kp, g_k);
    cudaGetSymbolAddress((void**)&vp, g_v);
    cudaGetSymbolAddress((void**)&zp, g_z);

    cudaFuncSetAttribute(tf32gemm128,
                         cudaFuncAttributeMaxDynamicSharedMemorySize, GEMM_SMEM);
    cudaFuncSetAttribute(flash_kernel,
                         cudaFuncAttributeMaxDynamicSharedMemorySize, FLASH_SMEM);

    dim3 gg(MROWS / 128, FEAT / 128);   // (32, 16)

    // QKV projections (per-head weight slabs: stride D*128, ldb=128)
    const long long projStride = (long long)ND * NDH;  // 262144
    tf32gemm128<<<gg, 256, GEMM_SMEM>>>(xq, WQ, bQ, qp, ND, ND, NDH, projStride, FEAT);
    tf32gemm128<<<gg, 256, GEMM_SMEM>>>(xk, WK, bK, kp, ND, ND, NDH, projStride, FEAT);
    tf32gemm128<<<gg, 256, GEMM_SMEM>>>(xv, WV, bV, vp, ND, ND, NDH, projStride, FEAT);

    // Rotary on q and k (4,194,304 pairs)
    rotary_kernel<<<16384, 256>>>(qp, kp);

    // Flash attention
    flash_kernel<<<dim3(NS / 64, NH, NB), 256, FLASH_SMEM>>>(qp, kp, vp, zp);

    // Output projection: z[4096,2048] @ W_O[2048,2048] + b_O
    tf32gemm128<<<gg, 256, GEMM_SMEM>>>(zp, WO, bO, out, FEAT, FEAT, ND, 128LL, ND);
}

// round 9
// speedup vs baseline: 1.3434x; 1.0739x over previous
#include <cuda_runtime.h>
#include <math.h>
#include <stdint.h>

// Problem constants
#define NB   2
#define NS   2048
#define ND   2048
#define NH   16
#define NDH  128
#define MROWS (NB*NS)        // 4096 flattened (b,s) rows
#define FEAT  (NH*NDH)       // 2048 flattened (h,e) features

// Scratch buffers (allocation-free rule: __device__ globals)
#define QKV_ELEMS 8388608ull  // 4096 * 2048
__device__ float g_q[QKV_ELEMS];
__device__ float g_k[QKV_ELEMS];
__device__ float g_v[QKV_ELEMS];
__device__ float g_z[QKV_ELEMS];

// ---------------------------------------------------------------------------
// Shared tf32 helpers
// ---------------------------------------------------------------------------
__device__ __forceinline__ void split_tf32(float x, uint32_t& hi, uint32_t& lo)
{
    uint32_t h;
    asm("cvt.rna.tf32.f32 %0, %1;" : "=r"(h) : "f"(x));
    float r = x - __uint_as_float(h);
    asm("cvt.rna.tf32.f32 %0, %1;" : "=r"(lo) : "f"(r));
    hi = h;
}

__device__ __forceinline__ void mma_tf32(float* d, const uint32_t* a, const uint32_t* b)
{
    asm volatile(
        "mma.sync.aligned.m16n8k8.row.col.f32.tf32.tf32.f32 "
        "{%0,%1,%2,%3}, {%4,%5,%6,%7}, {%8,%9}, {%0,%1,%2,%3};\n"
        : "+f"(d[0]), "+f"(d[1]), "+f"(d[2]), "+f"(d[3])
        : "r"(a[0]), "r"(a[1]), "r"(a[2]), "r"(a[3]), "r"(b[0]), "r"(b[1]));
}

__device__ __forceinline__ void cp16(uint32_t smem_addr, const void* gptr)
{
    asm volatile("cp.async.cg.shared.global [%0], [%1], 16;\n"
                 :: "r"(smem_addr), "l"(gptr));
}

// ---------------------------------------------------------------------------
// 3xTF32 tensor-core GEMM: C[4096 x 128-per-ntile] = A[4096 x K] * B + bias
// (unchanged from R6 — passing at rel_err 4.3e-5)
// ---------------------------------------------------------------------------
#define BK      32
#define APITCH  36
#define BPITCH  136
#define A_SM    (128 * APITCH)
#define B_SM    (BK * BPITCH)
#define BUF_SM  (A_SM + B_SM)
#define GEMM_SMEM (2 * BUF_SM * 4)    // 71680 bytes

__global__ __launch_bounds__(256) void tf32gemm128(
    const float* __restrict__ A, const float* __restrict__ B,
    const float* __restrict__ bias, float* __restrict__ C,
    int K, int lda, int ldb, long long btileStride, int ldc)
{
    extern __shared__ float sm[];
    const uint32_t sm_u = (uint32_t)__cvta_generic_to_shared(sm);

    const int tid  = threadIdx.x;
    const int lane = tid & 31;
    const int w    = tid >> 5;
    const int warpM = w >> 2;
    const int warpN = w & 3;
    const int g  = lane >> 2;
    const int tg = lane & 3;

    const int mtile = blockIdx.x, ntile = blockIdx.y;

    const float* Abase = A + (size_t)(mtile * 128) * lda;
    const float* Bbase = B + (size_t)ntile * btileStride;

    const int a_kq = tid & 7;
    const int a_m0 = tid >> 3;
    const int b_n4 = tid & 31;
    const int b_k0 = tid >> 5;

    float acc[16][4];
#pragma unroll
    for (int i = 0; i < 16; i++)
#pragma unroll
        for (int j = 0; j < 4; j++) acc[i][j] = 0.0f;

    const int nt_iters = K >> 5;

#define ISSUE_TILE(kt, bf)                                                        \
    {                                                                             \
        uint32_t abuf = sm_u + (uint32_t)((bf) * BUF_SM) * 4u;                    \
        uint32_t bbuf = abuf + (uint32_t)A_SM * 4u;                               \
        _Pragma("unroll")                                                         \
        for (int i = 0; i < 4; i++) {                                             \
            int m = a_m0 + 32 * i;                                                \
            cp16(abuf + (uint32_t)(m * APITCH + a_kq * 4) * 4u,                   \
                 Abase + (size_t)m * lda + (kt) * BK + a_kq * 4);                 \
        }                                                                         \
        _Pragma("unroll")                                                         \
        for (int i = 0; i < 4; i++) {                                             \
            int k = b_k0 + 8 * i;                                                 \
            cp16(bbuf + (uint32_t)(k * BPITCH + b_n4 * 4) * 4u,                   \
                 Bbase + (size_t)((kt) * BK + k) * ldb + b_n4 * 4);               \
        }                                                                         \
        asm volatile("cp.async.commit_group;\n" ::);                              \
    }

    ISSUE_TILE(0, 0);

    int buf = 0;
    for (int kt = 0; kt < nt_iters; kt++) {
        if (kt + 1 < nt_iters) {
            ISSUE_TILE(kt + 1, buf ^ 1);
            asm volatile("cp.async.wait_group 1;\n" ::);
        } else {
            asm volatile("cp.async.wait_group 0;\n" ::);
        }
        __syncthreads();

        const float* Asb = sm + buf * BUF_SM;
        const float* Bsb = Asb + A_SM;

#pragma unroll
        for (int ks = 0; ks < 4; ks++) {
            const int k0 = ks * 8;

            uint32_t bhi[4][2], blo[4][2];
#pragma unroll
            for (int nt = 0; nt < 4; nt++) {
                int n = warpN * 32 + nt * 8 + g;
                float b0 = Bsb[(k0 + tg) * BPITCH + n];
                float b1 = Bsb[(k0 + tg + 4) * BPITCH + n];
                split_tf32(b0, bhi[nt][0], blo[nt][0]);
                split_tf32(b1, bhi[nt][1], blo[nt][1]);
            }

#pragma unroll
            for (int mt = 0; mt < 4; mt++) {
                int m = warpM * 64 + mt * 16 + g;
                float a0 = Asb[m * APITCH + k0 + tg];
                float a1 = Asb[(m + 8) * APITCH + k0 + tg];
                float a2 = Asb[m * APITCH + k0 + tg + 4];
                float a3 = Asb[(m + 8) * APITCH + k0 + tg + 4];
                uint32_t ahi[4], alo[4];
                split_tf32(a0, ahi[0], alo[0]);
                split_tf32(a1, ahi[1], alo[1]);
                split_tf32(a2, ahi[2], alo[2]);
                split_tf32(a3, ahi[3], alo[3]);
#pragma unroll
                for (int nt = 0; nt < 4; nt++) {
                    float* d = acc[mt * 4 + nt];
                    mma_tf32(d, ahi, bhi[nt]);
                    mma_tf32(d, ahi, blo[nt]);
                    mma_tf32(d, alo, bhi[nt]);
                }
            }
        }

        __syncthreads();
        buf ^= 1;
    }

#pragma unroll
    for (int mt = 0; mt < 4; mt++) {
#pragma unroll
        for (int nt = 0; nt < 4; nt++) {
            const float* d = acc[mt * 4 + nt];
            int r0 = mtile * 128 + warpM * 64 + mt * 16 + g;
            int c  = ntile * 128 + warpN * 32 + nt * 8 + 2 * tg;
            float bx = bias[c], by = bias[c + 1];
            float2 lo = make_float2(d[0] + bx, d[1] + by);
            float2 hi = make_float2(d[2] + bx, d[3] + by);
            *(float2*)&C[(size_t)r0 * ldc + c]       = lo;
            *(float2*)&C[(size_t)(r0 + 8) * ldc + c] = hi;
        }
    }
}

// ---------------------------------------------------------------------------
// Rotary (in-place on q and k). Unchanged.
// ---------------------------------------------------------------------------
__global__ void rotary_kernel(float* __restrict__ q, float* __restrict__ k)
{
    int p = blockIdx.x * blockDim.x + threadIdx.x;
    int e = p & 63;
    int h = (p >> 6) & 15;
    int s = (p >> 10) & 2047;
    int b = p >> 21;

    float freq = powf(10000.0f, (float)e * (1.0f / 64.0f));
    float ang  = (float)s / freq;
    float sn, cs;
    sincosf(ang, &sn, &cs);

    size_t base = ((size_t)(b * NS + s) * NH + h) * NDH + e;

    float x0 = q[base], x1 = q[base + 64];
    q[base]      = x0 * cs - x1 * sn;
    q[base + 64] = x1 * cs + x0 * sn;

    x0 = k[base]; x1 = k[base + 64];
    k[base]      = x0 * cs - x1 * sn;
    k[base + 64] = x1 * cs + x0 * sn;
}

// ---------------------------------------------------------------------------
// Flash attention on TENSOR CORES (3xTF32, causal).
// Br=128 rows/CTA, Bc=64 keys/tile, 256 threads = 8 warps x 16 rows.
// S in mma accumulators -> softmax in accumulator layout (quad shuffles) ->
// P via per-warp smem buffer (producer==consumer) -> PV mma -> O in regs.
// Smem pitches chosen conflict-free: Q/K 132 (bank 4g+tg), V 136 (8tg+g),
// P 68 (4g+tg).
// ---------------------------------------------------------------------------
#define FQ_PITCH 132
#define FK_PITCH 132
#define FV_PITCH 136
#define FP_PITCH 68
#define FQ_OFF   0
#define FK_OFF   (128 * FQ_PITCH)                    // 16896
#define FV_OFF   (FK_OFF + 64 * FK_PITCH)            // 25344
#define FP_OFF   (FV_OFF + 64 * FV_PITCH)            // 34048
#define FLASH_FLOATS (FP_OFF + 8 * 16 * FP_PITCH)    // 42752
#define FLASH_SMEM  (FLASH_FLOATS * 4)               // 171008 bytes

__global__ __launch_bounds__(256, 1) void flash_tf32_kernel(
    const float* __restrict__ gq, const float* __restrict__ gk,
    const float* __restrict__ gv, float* __restrict__ gz)
{
    extern __shared__ float sm[];
    float* Qs = sm + FQ_OFF;
    float* Ks = sm + FK_OFF;
    float* Vs = sm + FV_OFF;

    const int tid  = threadIdx.x;
    const int lane = tid & 31;
    const int w    = tid >> 5;
    const int g    = lane >> 2;       // mma group (row within 8)
    const int tg   = lane & 3;        // thread-in-group
    const int qt   = blockIdx.x;      // 128-row query tile
    const int h    = blockIdx.y;
    const int b    = blockIdx.z;

    float* Pw = sm + FP_OFF + w * (16 * FP_PITCH);   // this warp's P buffer

    const size_t hb = (size_t)b * ((size_t)NS * NH * NDH) + (size_t)h * NDH;
    const float* qb = gq + hb;
    const float* kb = gk + hb;
    const float* vb = gv + hb;
    float* zb = gz + hb;

    const float scale = 0.08838834764831845f;   // 1/sqrt(128)
    const int ldrow = NH * NDH;                 // 2048

    // Load + pre-scale Q tile: 128 x 128 (4096 float4, 16/thread)
#pragma unroll
    for (int i = 0; i < 16; i++) {
        int idx = tid + 256 * i;
        int r = idx >> 5, c4 = idx & 31;
        float4 qv = *(const float4*)(qb + (size_t)(qt * 128 + r) * ldrow + c4 * 4);
        qv.x *= scale; qv.y *= scale; qv.z *= scale; qv.w *= scale;
        *(float4*)&Qs[r * FQ_PITCH + c4 * 4] = qv;
    }

    float O[16][4];
#pragma unroll
    for (int i = 0; i < 16; i++)
#pragma unroll
        for (int j2 = 0; j2 < 4; j2++) O[i][j2] = 0.0f;
    float m0 = -INFINITY, m1 = -INFINITY, l0 = 0.0f, l1 = 0.0f;

    const int r0g = qt * 128 + w * 16 + g;      // this thread's global row 0
    const int r1g = r0g + 8;                    // global row 1
    const int warp_rhi = qt * 128 + w * 16 + 15;
    const int jmax = 2 * qt + 1;

    for (int j = 0; j <= jmax; j++) {
        __syncthreads();
        // Load K,V tiles: 64 x 128 each (2048 float4, 8/thread each)
#pragma unroll
        for (int i = 0; i < 8; i++) {
            int idx = tid + 256 * i;
            int r = idx >> 5, c4 = idx & 31;
            size_t gofs = (size_t)(j * 64 + r) * ldrow + c4 * 4;
            *(float4*)&Ks[r * FK_PITCH + c4 * 4] = *(const float4*)(kb + gofs);
            *(float4*)&Vs[r * FV_PITCH + c4 * 4] = *(const float4*)(vb + gofs);
        }
        __syncthreads();

        if (j * 64 > warp_rhi) continue;   // warp-uniform: tile fully masked

        // ---- S = Q K^T (3x split), S[16 rows x 64 keys] per warp ----
        float sacc[8][4];
#pragma unroll
        for (int nt = 0; nt < 8; nt++)
#pragma unroll
            for (int v = 0; v < 4; v++) sacc[nt][v] = 0.0f;

#pragma unroll
        for (int ks = 0; ks < 16; ks++) {
            const int k0 = ks * 8;
            const int m = w * 16 + g;
            float a0 = Qs[m * FQ_PITCH + k0 + tg];
            float a1 = Qs[(m + 8) * FQ_PITCH + k0 + tg];
            float a2 = Qs[m * FQ_PITCH + k0 + tg + 4];
            float a3 = Qs[(m + 8) * FQ_PITCH + k0 + tg + 4];
            uint32_t ahi[4], alo[4];
            split_tf32(a0, ahi[0], alo[0]);
            split_tf32(a1, ahi[1], alo[1]);
            split_tf32(a2, ahi[2], alo[2]);
            split_tf32(a3, ahi[3], alo[3]);
#pragma unroll
            for (int nt = 0; nt < 8; nt++) {
                int n = nt * 8 + g;
                float b0 = Ks[n * FK_PITCH + k0 + tg];
                float b1 = Ks[n * FK_PITCH + k0 + tg + 4];
                uint32_t bhi[2], blo[2];
                split_tf32(b0, bhi[0], blo[0]);
                split_tf32(b1, bhi[1], blo[1]);
                mma_tf32(sacc[nt], ahi, bhi);
                mma_tf32(sacc[nt], ahi, blo);
                mma_tf32(sacc[nt], alo, bhi);
            }
        }

        // ---- causal mask on diagonal tiles ----
        if (j * 64 + 63 > r0g) {
#pragma unroll
            for (int nt = 0; nt < 8; nt++) {
                int c = j * 64 + nt * 8 + 2 * tg;
                if (c > r0g)     sacc[nt][0] = -1e30f;
                if (c + 1 > r0g) sacc[nt][1] = -1e30f;
                if (c > r1g)     sacc[nt][2] = -1e30f;
                if (c + 1 > r1g) sacc[nt][3] = -1e30f;
            }
        }

        // ---- online softmax in accumulator layout ----
        float rmax0 = -1e30f, rmax1 = -1e30f;
#pragma unroll
        for (int nt = 0; nt < 8; nt++) {
            rmax0 = fmaxf(rmax0, fmaxf(sacc[nt][0], sacc[nt][1]));
            rmax1 = fmaxf(rmax1, fmaxf(sacc[nt][2], sacc[nt][3]));
        }
        rmax0 = fmaxf(rmax0, __shfl_xor_sync(0xffffffffu, rmax0, 1));
        rmax0 = fmaxf(rmax0, __shfl_xor_sync(0xffffffffu, rmax0, 2));
        rmax1 = fmaxf(rmax1, __shfl_xor_sync(0xffffffffu, rmax1, 1));
        rmax1 = fmaxf(rmax1, __shfl_xor_sync(0xffffffffu, rmax1, 2));

        float mn0 = fmaxf(m0, rmax0), mn1 = fmaxf(m1, rmax1);
        float alpha0 = __expf(m0 - mn0), alpha1 = __expf(m1 - mn1);

        float ps0 = 0.0f, ps1 = 0.0f;
#pragma unroll
        for (int nt = 0; nt < 8; nt++) {
            float p0 = __expf(sacc[nt][0] - mn0);
            float p1 = __expf(sacc[nt][1] - mn0);
            float p2 = __expf(sacc[nt][2] - mn1);
            float p3 = __expf(sacc[nt][3] - mn1);
            ps0 += p0 + p1;
            ps1 += p2 + p3;
            *(float2*)&Pw[g * FP_PITCH + nt * 8 + 2 * tg]       = make_float2(p0, p1);
            *(float2*)&Pw[(g + 8) * FP_PITCH + nt * 8 + 2 * tg] = make_float2(p2, p3);
        }
        ps0 += __shfl_xor_sync(0xffffffffu, ps0, 1);
        ps0 += __shfl_xor_sync(0xffffffffu, ps0, 2);
        ps1 += __shfl_xor_sync(0xffffffffu, ps1, 1);
        ps1 += __shfl_xor_sync(0xffffffffu, ps1, 2);

        l0 = l0 * alpha0 + ps0;  m0 = mn0;
        l1 = l1 * alpha1 + ps1;  m1 = mn1;

#pragma unroll
        for (int nt = 0; nt < 16; nt++) {
            O[nt][0] *= alpha0; O[nt][1] *= alpha0;
            O[nt][2] *= alpha1; O[nt][3] *= alpha1;
        }
        __syncwarp();   // P buffer visible to whole warp

        // ---- O += P V (3x split), O[16 rows x 128 dims] per warp ----
#pragma unroll
        for (int ks = 0; ks < 8; ks++) {
            const int k0 = ks * 8;
            float a0 = Pw[g * FP_PITCH + k0 + tg];
            float a1 = Pw[(g + 8) * FP_PITCH + k0 + tg];
            float a2 = Pw[g * FP_PITCH + k0 + tg + 4];
            float a3 = Pw[(g + 8) * FP_PITCH + k0 + tg + 4];
            uint32_t ahi[4], alo[4];
            split_tf32(a0, ahi[0], alo[0]);
            split_tf32(a1, ahi[1], alo[1]);
            split_tf32(a2, ahi[2], alo[2]);
            split_tf32(a3, ahi[3], alo[3]);
#pragma unroll
            for (int nt = 0; nt < 16; nt++) {
                int n = nt * 8 + g;
                float b0 = Vs[(k0 + tg) * FV_PITCH + n];
                float b1 = Vs[(k0 + tg + 4) * FV_PITCH + n];
                uint32_t bhi[2], blo[2];
                split_tf32(b0, bhi[0], blo[0]);
                split_tf32(b1, bhi[1], blo[1]);
                mma_tf32(O[nt], ahi, bhi);
                mma_tf32(O[nt], ahi, blo);
                mma_tf32(O[nt], alo, bhi);
            }
        }
        __syncwarp();   // P fully consumed before next j overwrites it
    }

    // ---- epilogue: normalize and store ----
    float inv0 = 1.0f / l0, inv1 = 1.0f / l1;
#pragma unroll
    for (int nt = 0; nt < 16; nt++) {
        int c = nt * 8 + 2 * tg;
        *(float2*)&zb[(size_t)r0g * ldrow + c] =
            make_float2(O[nt][0] * inv0, O[nt][1] * inv0);
        *(float2*)&zb[(size_t)r1g * ldrow + c] =
            make_float2(O[nt][2] * inv1, O[nt][3] * inv1);
    }
}

// ---------------------------------------------------------------------------
// Launcher
// ---------------------------------------------------------------------------
extern "C" void kernel_launch(void* const* d_in, const int* in_sizes, int n_in,
                              void* d_out, int out_size)
{
    const float* xq = (const float*)d_in[0];
    const float* xk = (const float*)d_in[1];
    const float* xv = (const float*)d_in[2];
    const float* WQ = (const float*)d_in[3];
    const float* WK = (const float*)d_in[4];
    const float* WV = (const float*)d_in[5];
    const float* WO = (const float*)d_in[6];
    const float* bQ = (const float*)d_in[7];
    const float* bK = (const float*)d_in[8];
    const float* bV = (const float*)d_in[9];
    const float* bO = (const float*)d_in[10];
    float* out = (float*)d_out;

    float *qp, *kp, *vp, *zp;
    cudaGetSymbolAddress((void**)&qp, g_q);
    cudaGetSymbolAddress((void**)&kp, g_k);
    cudaGetSymbolAddress((void**)&vp, g_v);
    cudaGetSymbolAddress((void**)&zp, g_z);

    cudaFuncSetAttribute(tf32gemm128,
                         cudaFuncAttributeMaxDynamicSharedMemorySize, GEMM_SMEM);
    cudaFuncSetAttribute(flash_tf32_kernel,
                         cudaFuncAttributeMaxDynamicSharedMemorySize, FLASH_SMEM);

    dim3 gg(MROWS / 128, FEAT / 128);   // (32, 16)

    // QKV projections (per-head weight slabs: stride D*128, ldb=128)
    const long long projStride = (long long)ND * NDH;  // 262144
    tf32gemm128<<<gg, 256, GEMM_SMEM>>>(xq, WQ, bQ, qp, ND, ND, NDH, projStride, FEAT);
    tf32gemm128<<<gg, 256, GEMM_SMEM>>>(xk, WK, bK, kp, ND, ND, NDH, projStride, FEAT);
    tf32gemm128<<<gg, 256, GEMM_SMEM>>>(xv, WV, bV, vp, ND, ND, NDH, projStride, FEAT);

    // Rotary on q and k
    rotary_kernel<<<16384, 256>>>(qp, kp);

    // Flash attention (tensor cores, 128-row query tiles)
    flash_tf32_kernel<<<dim3(NS / 128, NH, NB), 256, FLASH_SMEM>>>(qp, kp, vp, zp);

    // Output projection
    tf32gemm128<<<gg, 256, GEMM_SMEM>>>(zp, WO, bO, out, FEAT, FEAT, ND, 128LL, ND);
}